// round 3
// baseline (speedup 1.0000x reference)
#include <cuda_runtime.h>
#include <math.h>

// Problem constants
#define PB   8
#define PSL  512
#define PH   768
#define PNS  256
#define PW   32
#define PNH  12
#define PHD  64
#define PFFN 3072
#define PN   2048   // PB*PNS

// ---------------- scratch (device globals: no allocations allowed) ----------
__device__ float g_tokpe[PB * PSL * PH];        // token + positional encoding
__device__ float g_qproj[PH];                    // q = Wq q0 + bq
__device__ float g_u[PNH * PH];                  // u_h = Wk_h^T q_h
__device__ float g_c[PNH];                       // c_h = q_h . bk_h
__device__ float g_p[(size_t)PNH * PN * PH];     // pooled spans, head-major [h][n][e]
__device__ float g_ctx[(size_t)PN * PH];
__device__ float g_att[(size_t)PN * PH];
__device__ float g_x1[(size_t)PN * PH];
__device__ float g_hmid[(size_t)PN * PFFN];
__device__ float g_z[(size_t)PN * PH];

// ---------------- K0a: tok + PE ---------------------------------------------
__global__ void tokpe_kernel(const float* __restrict__ tok) {
    int r = blockIdx.x;            // 0 .. B*SL-1
    int pos = r % PSL;
    size_t base = (size_t)r * PH;
    for (int c = threadIdx.x; c < PH; c += blockDim.x) {
        int i2 = (c >> 1) * 2;
        float div = expf((float)i2 * (-9.210340371976184f / (float)PH));
        float ang = (float)pos * div;
        float pe = (c & 1) ? cosf(ang) : sinf(ang);
        g_tokpe[base + c] = tok[base + c] + pe;
    }
}

// ---------------- K0b: q projection (warp per output row) -------------------
__global__ void qproj_kernel(const float* __restrict__ w, const float* __restrict__ b,
                             const float* __restrict__ q0) {
    int gt   = blockIdx.x * blockDim.x + threadIdx.x;
    int warp = gt >> 5;
    int lane = gt & 31;
    if (warp >= PH) return;
    const float* wr = w + (size_t)warp * PH;   // Wq row
    float acc = 0.f;
    for (int e = lane; e < PH; e += 32) acc += wr[e] * q0[e];
    #pragma unroll
    for (int o = 16; o; o >>= 1) acc += __shfl_xor_sync(0xffffffffu, acc, o);
    if (!lane) g_qproj[warp] = acc + b[warp];
}

// ---------------- K0c: u_h, c_h ---------------------------------------------
__global__ void uprep_kernel(const float* __restrict__ w, const float* __restrict__ b) {
    int idx = blockIdx.x * blockDim.x + threadIdx.x;
    if (idx < PNH * PH) {
        int h = idx / PH, e = idx % PH;
        float acc = 0.f;
        #pragma unroll 8
        for (int d = 0; d < PHD; d++)
            acc += w[((size_t)(PH + h * PHD + d)) * PH + e] * g_qproj[h * PHD + d];
        g_u[idx] = acc;
    }
    if (idx < PNH) {
        float acc = 0.f;
        #pragma unroll 8
        for (int d = 0; d < PHD; d++)
            acc += g_qproj[idx * PHD + d] * b[PH + idx * PHD + d];
        g_c[idx] = acc;
    }
}

// ---------------- K1: per-span gather + scores + softmax + pooling ----------
// NOTE: span_ids is int32 on device (JAX x64 disabled: astype(int64) -> int32).
// smem: spans[32][768] + scores[12*32]
#define SPAN_SMEM ((PW * PH + PNH * PW) * sizeof(float))
__global__ __launch_bounds__(256) void span_kernel(const int* __restrict__ ids) {
    extern __shared__ float sm[];
    float* spans = sm;                  // 32*768
    float* sc    = sm + PW * PH;        // 12*32 scores -> attn (in place)

    int n = blockIdx.x;
    int b = n / PNS;
    int tid = threadIdx.x;

    int start = ids[2 * n];
    int len   = ids[2 * n + 1] - start;

    const float* base = g_tokpe + (size_t)b * PSL * PH;

    // gather (vectorized), zero invalid rows
    const int nv4 = PW * PH / 4;   // 6144
    for (int i = tid; i < nv4; i += 256) {
        int w  = i / (PH / 4);
        int c4 = i % (PH / 4);
        float4 v;
        if (w < len) {
            int p = start + w;
            p = p < 0 ? 0 : (p > PSL - 1 ? PSL - 1 : p);
            v = *(const float4*)(base + (size_t)p * PH + c4 * 4);
        } else {
            v = make_float4(0.f, 0.f, 0.f, 0.f);
        }
        *(float4*)(spans + (size_t)w * PH + c4 * 4) = v;
    }
    __syncthreads();

    // scores[h][w] = (spans_w . u_h + c_h)/8, masked
    int warp = tid >> 5, lane = tid & 31;
    for (int i = warp; i < PNH * PW; i += 8) {
        int h = i >> 5, w = i & 31;     // i = h*32 + w
        const float* sp = spans + w * PH;
        const float* uh = g_u + h * PH;
        float acc = 0.f;
        for (int e = lane; e < PH; e += 32) acc += sp[e] * __ldg(uh + e);
        #pragma unroll
        for (int o = 16; o; o >>= 1) acc += __shfl_xor_sync(0xffffffffu, acc, o);
        if (!lane) sc[i] = (w < len) ? (acc + g_c[h]) * 0.125f : -1e9f;
    }
    __syncthreads();

    // softmax over w per head
    if (tid < PNH) {
        float mx = -3.4e38f;
        for (int w = 0; w < PW; w++) mx = fmaxf(mx, sc[tid * PW + w]);
        float s = 0.f;
        for (int w = 0; w < PW; w++) {
            float e = expf(sc[tid * PW + w] - mx);
            sc[tid * PW + w] = e;
            s += e;
        }
        float inv = 1.0f / s;
        for (int w = 0; w < PW; w++) sc[tid * PW + w] *= inv;
    }
    __syncthreads();

    // p[h][n][e] = sum_w attn[h][w] * spans[w][e]
    for (int i = tid; i < PNH * PH; i += 256) {
        int h = i / PH, e = i % PH;
        float acc = 0.f;
        #pragma unroll
        for (int w = 0; w < PW; w++) acc += sc[h * PW + w] * spans[w * PH + e];
        g_p[((size_t)h * PN + n) * PH + e] = acc;
    }
}

// ---------------- generic tiled GEMM: C = A @ B^T (+bias)(+resid)(relu) -----
// A: M x K row-major (lda), B: N x K row-major (ldb), C: M x N (ldc)
// batched via blockIdx.z with element strides sA (A), sB (B), sC (C col offset),
// sBias (bias offset). resid indexed [m*ldr + n] (ldr=0 -> broadcast row).
#define GBM 128
#define GBN 64
#define GBK 16
__global__ __launch_bounds__(128) void gemm_bt_kernel(
    const float* __restrict__ A, const float* __restrict__ Bm,
    const float* __restrict__ bias, const float* __restrict__ resid,
    float* __restrict__ C,
    int M, int N, int K, int lda, int ldb, int ldc, int ldr,
    long long sA, long long sB, long long sC, long long sBias, int relu)
{
    __shared__ float As[GBK][GBM + 4];
    __shared__ float Bs[GBK][GBN + 4];

    int z = blockIdx.z;
    const float* Ab = A + (size_t)z * sA;
    const float* Bb = Bm + (size_t)z * sB;
    float* Cb = C + (size_t)z * sC;
    const float* biasb = bias ? bias + (size_t)z * sBias : (const float*)0;

    int m0 = blockIdx.y * GBM;
    int n0 = blockIdx.x * GBN;
    int tid = threadIdx.x;
    int tx = tid & 7;       // 8 cols of threads
    int ty = tid >> 3;      // 16 rows of threads

    float acc[8][8];
    #pragma unroll
    for (int i = 0; i < 8; i++)
        #pragma unroll
        for (int j = 0; j < 8; j++) acc[i][j] = 0.f;

    for (int k0 = 0; k0 < K; k0 += GBK) {
        // A tile: 128x16 = 512 float4, 4 per thread
        #pragma unroll
        for (int j = 0; j < 4; j++) {
            int f = tid + j * 128;
            int row = f >> 2;
            int kc = (f & 3) * 4;
            float4 v = *(const float4*)(Ab + (size_t)(m0 + row) * lda + k0 + kc);
            As[kc + 0][row] = v.x; As[kc + 1][row] = v.y;
            As[kc + 2][row] = v.z; As[kc + 3][row] = v.w;
        }
        // B tile: 64x16 = 256 float4, 2 per thread
        #pragma unroll
        for (int j = 0; j < 2; j++) {
            int f = tid + j * 128;
            int row = f >> 2;
            int kc = (f & 3) * 4;
            float4 v = *(const float4*)(Bb + (size_t)(n0 + row) * ldb + k0 + kc);
            Bs[kc + 0][row] = v.x; Bs[kc + 1][row] = v.y;
            Bs[kc + 2][row] = v.z; Bs[kc + 3][row] = v.w;
        }
        __syncthreads();
        #pragma unroll
        for (int k = 0; k < GBK; k++) {
            float a[8], bb[8];
            #pragma unroll
            for (int i = 0; i < 8; i++) a[i] = As[k][ty * 8 + i];
            #pragma unroll
            for (int j = 0; j < 8; j++) bb[j] = Bs[k][tx * 8 + j];
            #pragma unroll
            for (int i = 0; i < 8; i++)
                #pragma unroll
                for (int j = 0; j < 8; j++) acc[i][j] += a[i] * bb[j];
        }
        __syncthreads();
    }

    // epilogue
    #pragma unroll
    for (int i = 0; i < 8; i++) {
        int m = m0 + ty * 8 + i;
        #pragma unroll
        for (int j = 0; j < 8; j++) {
            int nn = n0 + tx * 8 + j;
            float cv = acc[i][j];
            if (biasb) cv += biasb[nn];
            if (resid) cv += resid[(size_t)m * ldr + nn];
            if (relu)  cv = fmaxf(cv, 0.f);
            Cb[(size_t)m * ldc + nn] = cv;
        }
    }
}

// ---------------- LayerNorm (optionally masked by span length) --------------
__global__ __launch_bounds__(256) void ln_kernel(
    const float* __restrict__ in, const float* __restrict__ gamma,
    const float* __restrict__ beta, const int* __restrict__ ids,
    float* __restrict__ out)
{
    __shared__ float red1[8], red2[8];
    __shared__ float bc1, bc2;
    int row = blockIdx.x, tid = threadIdx.x;
    const float* x = in + (size_t)row * PH;

    float v[3];
    #pragma unroll
    for (int j = 0; j < 3; j++) v[j] = x[tid + j * 256];

    float s = v[0] + v[1] + v[2];
    #pragma unroll
    for (int o = 16; o; o >>= 1) s += __shfl_xor_sync(0xffffffffu, s, o);
    if ((tid & 31) == 0) red1[tid >> 5] = s;
    __syncthreads();
    if (tid < 8) {
        float t = red1[tid];
        #pragma unroll
        for (int o = 4; o; o >>= 1) t += __shfl_xor_sync(0xffu, t, o);
        if (!tid) bc1 = t;
    }
    __syncthreads();
    float mu = bc1 * (1.0f / PH);

    float d0 = v[0] - mu, d1 = v[1] - mu, d2 = v[2] - mu;
    float sq = d0 * d0 + d1 * d1 + d2 * d2;
    #pragma unroll
    for (int o = 16; o; o >>= 1) sq += __shfl_xor_sync(0xffffffffu, sq, o);
    if ((tid & 31) == 0) red2[tid >> 5] = sq;
    __syncthreads();
    if (tid < 8) {
        float t = red2[tid];
        #pragma unroll
        for (int o = 4; o; o >>= 1) t += __shfl_xor_sync(0xffu, t, o);
        if (!tid) bc2 = t;
    }
    __syncthreads();
    float var = bc2 * (1.0f / PH);
    float rs = rsqrtf(var + 1e-5f);

    float mask = 1.0f;
    if (ids) {
        int a = ids[2 * row], b = ids[2 * row + 1];
        if (b - a <= 0) mask = 0.f;
    }
    #pragma unroll
    for (int j = 0; j < 3; j++) {
        int c = tid + j * 256;
        out[(size_t)row * PH + c] = ((v[j] - mu) * rs * gamma[c] + beta[c]) * mask;
    }
}

// ---------------- launch -----------------------------------------------------
extern "C" void kernel_launch(void* const* d_in, const int* in_sizes, int n_in,
                              void* d_out, int out_size) {
    const float* tok = (const float*)d_in[0];
    const int*   ids = (const int*)d_in[1];     // int32! (JAX x64 disabled)
    const float* q0  = (const float*)d_in[2];
    const float* inw = (const float*)d_in[3];
    const float* inb = (const float*)d_in[4];
    const float* ow  = (const float*)d_in[5];
    const float* ob  = (const float*)d_in[6];
    const float* lng = (const float*)d_in[7];
    const float* lnb = (const float*)d_in[8];
    const float* w1  = (const float*)d_in[9];
    const float* b1  = (const float*)d_in[10];
    const float* w2  = (const float*)d_in[11];
    const float* b2  = (const float*)d_in[12];
    float* out = (float*)d_out;

    float *p_p, *p_ctx, *p_att, *p_x1, *p_h, *p_z;
    cudaGetSymbolAddress((void**)&p_p,   g_p);
    cudaGetSymbolAddress((void**)&p_ctx, g_ctx);
    cudaGetSymbolAddress((void**)&p_att, g_att);
    cudaGetSymbolAddress((void**)&p_x1,  g_x1);
    cudaGetSymbolAddress((void**)&p_h,   g_hmid);
    cudaGetSymbolAddress((void**)&p_z,   g_z);

    // K0: tok+pe, q projection, u/c prep
    tokpe_kernel<<<PB * PSL, 256>>>(tok);
    qproj_kernel<<<96, 256>>>(inw, inb, q0);
    uprep_kernel<<<36, 256>>>(inw, inb);

    // K1: per-span pooling
    cudaFuncSetAttribute(span_kernel, cudaFuncAttributeMaxDynamicSharedMemorySize,
                         (int)SPAN_SMEM);
    span_kernel<<<PN, 256, SPAN_SMEM>>>(ids);

    // K2: ctx[n, h*64+d] = Wv_h @ p[n,h] + bv   (batched over heads)
    gemm_bt_kernel<<<dim3(1, PN / GBM, PNH), 128>>>(
        p_p, inw + (size_t)2 * PH * PH, inb + 2 * PH, (const float*)0, p_ctx,
        PN, PHD, PH, PH, PH, PH, 0,
        (long long)PN * PH, (long long)PHD * PH, PHD, PHD, 0);

    // K3: attn_out = ctx @ O^T + ob + q0(broadcast)
    gemm_bt_kernel<<<dim3(PH / GBN, PN / GBM, 1), 128>>>(
        p_ctx, ow, ob, q0, p_att,
        PN, PH, PH, PH, PH, PH, 0, 0, 0, 0, 0, 0);

    // K4: x1 = LN(attn_out)
    ln_kernel<<<PN, 256>>>(p_att, lng, lnb, (const int*)0, p_x1);

    // K5: h = relu(x1 @ W1^T + b1)
    gemm_bt_kernel<<<dim3(PFFN / GBN, PN / GBM, 1), 128>>>(
        p_x1, w1, b1, (const float*)0, p_h,
        PN, PFFN, PH, PH, PH, PFFN, 0, 0, 0, 0, 0, 1);

    // K6: z = h @ W2^T + b2 + x1
    gemm_bt_kernel<<<dim3(PH / GBN, PN / GBM, 1), 128>>>(
        p_h, w2, b2, p_x1, p_z,
        PN, PH, PFFN, PFFN, PFFN, PH, PH, 0, 0, 0, 0, 0);

    // K7: out = LN(z) masked by length>0
    ln_kernel<<<PN, 256>>>(p_z, lng, lnb, ids, out);
}

// round 4
// speedup vs baseline: 3.1401x; 3.1401x over previous
#include <cuda_runtime.h>
#include <math.h>

// Problem constants
#define PB   8
#define PSL  512
#define PH   768
#define PNS  256
#define PW   32
#define PNH  12
#define PHD  64
#define PFFN 3072
#define PN   2048   // PB*PNS

// ---------------- scratch (device globals) ----------------------------------
__device__ float g_tokpe[PB * PSL * PH];
__device__ float g_qproj[PH];
__device__ float g_u[PNH * PH];
__device__ float g_c[PNH];
__device__ float g_T[PB * PSL * PNH];            // tokpe . u_h for every position
__device__ float g_p[(size_t)PNH * PN * PH];     // pooled spans, head-major
__device__ float g_ctx[(size_t)PN * PH];
__device__ float g_att[(size_t)PN * PH];
__device__ float g_x1[(size_t)PN * PH];
__device__ float g_hmid[(size_t)PN * PFFN];
__device__ float g_z[(size_t)PN * PH];

// ---------------- K0a: tok + PE ---------------------------------------------
__global__ void tokpe_kernel(const float* __restrict__ tok) {
    int r = blockIdx.x;
    int pos = r % PSL;
    size_t base = (size_t)r * PH;
    for (int c = threadIdx.x; c < PH; c += blockDim.x) {
        int i2 = (c >> 1) * 2;
        float div = expf((float)i2 * (-9.210340371976184f / (float)PH));
        float ang = (float)pos * div;
        float pe = (c & 1) ? cosf(ang) : sinf(ang);
        g_tokpe[base + c] = tok[base + c] + pe;
    }
}

// ---------------- K0b: q projection -----------------------------------------
__global__ void qproj_kernel(const float* __restrict__ w, const float* __restrict__ b,
                             const float* __restrict__ q0) {
    int gt   = blockIdx.x * blockDim.x + threadIdx.x;
    int warp = gt >> 5;
    int lane = gt & 31;
    if (warp >= PH) return;
    const float* wr = w + (size_t)warp * PH;
    float acc = 0.f;
    for (int e = lane; e < PH; e += 32) acc += wr[e] * q0[e];
    #pragma unroll
    for (int o = 16; o; o >>= 1) acc += __shfl_xor_sync(0xffffffffu, acc, o);
    if (!lane) g_qproj[warp] = acc + b[warp];
}

// ---------------- K0c: u_h, c_h ---------------------------------------------
__global__ void uprep_kernel(const float* __restrict__ w, const float* __restrict__ b) {
    int idx = blockIdx.x * blockDim.x + threadIdx.x;
    if (idx < PNH * PH) {
        int h = idx / PH, e = idx % PH;
        float acc = 0.f;
        #pragma unroll 8
        for (int d = 0; d < PHD; d++)
            acc += w[((size_t)(PH + h * PHD + d)) * PH + e] * g_qproj[h * PHD + d];
        g_u[idx] = acc;
    }
    if (idx < PNH) {
        float acc = 0.f;
        #pragma unroll 8
        for (int d = 0; d < PHD; d++)
            acc += g_qproj[idx * PHD + d] * b[PH + idx * PHD + d];
        g_c[idx] = acc;
    }
}

// ---------------- K0d: T[b,pos,h] = tokpe[b,pos] . u_h ----------------------
__global__ __launch_bounds__(128) void tproj_kernel() {
    int row  = blockIdx.x * 4 + (threadIdx.x >> 5);   // 0 .. 4095
    int lane = threadIdx.x & 31;
    const float4* rp = (const float4*)g_tokpe + (size_t)row * (PH / 4);
    float4 rr[6];
    #pragma unroll
    for (int j = 0; j < 6; j++) rr[j] = rp[lane + 32 * j];
    #pragma unroll
    for (int h = 0; h < PNH; h++) {
        const float4* up = (const float4*)g_u + h * (PH / 4);
        float acc = 0.f;
        #pragma unroll
        for (int j = 0; j < 6; j++) {
            float4 u4 = __ldg(up + lane + 32 * j);
            acc += rr[j].x * u4.x + rr[j].y * u4.y + rr[j].z * u4.z + rr[j].w * u4.w;
        }
        #pragma unroll
        for (int o = 16; o; o >>= 1) acc += __shfl_xor_sync(0xffffffffu, acc, o);
        if (!lane) g_T[row * PNH + h] = acc;
    }
}

// ---------------- K1: span scores + softmax + pooling (no smem tile) --------
__global__ __launch_bounds__(192) void span_kernel(const int* __restrict__ ids) {
    __shared__ float s_att[PNH * PW];
    int n = blockIdx.x;
    int b = n >> 8;             // / PNS
    int tid = threadIdx.x;
    int start = ids[2 * n];
    int len   = ids[2 * n + 1] - start;

    // scores from precomputed T
    for (int i = tid; i < PNH * PW; i += 192) {
        int h = i >> 5, w = i & 31;
        float v = -1e9f;
        if (w < len)
            v = (g_T[(b * PSL + start + w) * PNH + h] + g_c[h]) * 0.125f;
        s_att[h * PW + w] = v;
    }
    __syncthreads();

    // softmax: warp per head
    int warp = tid >> 5, lane = tid & 31;
    for (int h = warp; h < PNH; h += 6) {
        float v = s_att[h * PW + lane];
        float mx = v;
        #pragma unroll
        for (int o = 16; o; o >>= 1) mx = fmaxf(mx, __shfl_xor_sync(0xffffffffu, mx, o));
        float e = __expf(v - mx);
        float s = e;
        #pragma unroll
        for (int o = 16; o; o >>= 1) s += __shfl_xor_sync(0xffffffffu, s, o);
        s_att[h * PW + lane] = e / s;
    }
    __syncthreads();

    // pooling: thread owns 4 consecutive e's; read each token row once,
    // accumulate all 12 heads in registers.
    const float4* base = (const float4*)g_tokpe + ((size_t)(b * PSL + start)) * (PH / 4);
    float4 acc[PNH];
    #pragma unroll
    for (int h = 0; h < PNH; h++) acc[h] = make_float4(0.f, 0.f, 0.f, 0.f);

    #pragma unroll 4
    for (int w = 0; w < PW; w++) {
        float4 v = base[(size_t)w * (PH / 4) + tid];
        #pragma unroll
        for (int h = 0; h < PNH; h++) {
            float a = s_att[h * PW + w];
            acc[h].x += a * v.x; acc[h].y += a * v.y;
            acc[h].z += a * v.z; acc[h].w += a * v.w;
        }
    }
    #pragma unroll
    for (int h = 0; h < PNH; h++)
        ((float4*)g_p)[((size_t)h * PN + n) * (PH / 4) + tid] = acc[h];
}

// ---------------- tf32 tensor-core GEMM: C = A @ B^T (+bias)(+resid)(relu) --
// Tile 128(M) x 64(N) x 32(K); 256 threads = 8 warps (4m x 2n); warp tile 32x32.
#define TBM 128
#define TBN 64
#define TBK 32
#define ASTR (TBK + 4)   // 36 floats, conflict-free
#define SMEM_GEMM ((2 * TBM * ASTR + 2 * TBN * ASTR) * 4)

__device__ __forceinline__ unsigned f2tf(float f) {
    unsigned u;
    asm("cvt.rna.tf32.f32 %0, %1;" : "=r"(u) : "f"(f));
    return u;
}

__global__ __launch_bounds__(256) void gemm_tf32_kernel(
    const float* __restrict__ A, const float* __restrict__ Bm,
    const float* __restrict__ bias, const float* __restrict__ resid,
    float* __restrict__ C,
    int K, int lda, int ldb, int ldc, int ldr,
    long long sA, long long sB, long long sC, long long sBias, int relu)
{
    extern __shared__ float sm[];
    float* As = sm;                       // [2][TBM][ASTR]
    float* Bs = sm + 2 * TBM * ASTR;      // [2][TBN][ASTR]

    int z = blockIdx.z;
    const float* Ab = A + (size_t)z * sA;
    const float* Bb = Bm + (size_t)z * sB;
    float* Cb = C + (size_t)z * sC;
    const float* biasb = bias ? bias + (size_t)z * sBias : (const float*)0;

    int m0 = blockIdx.y * TBM;
    int n0 = blockIdx.x * TBN;
    int tid  = threadIdx.x;
    int warp = tid >> 5, lane = tid & 31;
    int grp = lane >> 2, tig = lane & 3;
    int wm = warp & 3, wn = warp >> 2;

    float acc[2][4][4];
    #pragma unroll
    for (int mt = 0; mt < 2; mt++)
        #pragma unroll
        for (int nt = 0; nt < 4; nt++)
            #pragma unroll
            for (int r = 0; r < 4; r++) acc[mt][nt][r] = 0.f;

    // load indices
    int am = tid >> 3;               // for A: f = tid + 256j -> m = am + 32j
    int akc = (tid & 7) * 4;
    int bn = tid >> 3;               // for B: n = bn + 32j (j<2)

    float4 la[4], lb[2];
    int nIt = K / TBK;

    // prologue: tile 0
    #pragma unroll
    for (int j = 0; j < 4; j++)
        la[j] = *(const float4*)(Ab + (size_t)(m0 + am + 32 * j) * lda + akc);
    #pragma unroll
    for (int j = 0; j < 2; j++)
        lb[j] = *(const float4*)(Bb + (size_t)(n0 + bn + 32 * j) * ldb + akc);
    #pragma unroll
    for (int j = 0; j < 4; j++) {
        float4 t; t.x = __uint_as_float(f2tf(la[j].x)); t.y = __uint_as_float(f2tf(la[j].y));
        t.z = __uint_as_float(f2tf(la[j].z)); t.w = __uint_as_float(f2tf(la[j].w));
        *(float4*)&As[(size_t)(am + 32 * j) * ASTR + akc] = t;
    }
    #pragma unroll
    for (int j = 0; j < 2; j++) {
        float4 t; t.x = __uint_as_float(f2tf(lb[j].x)); t.y = __uint_as_float(f2tf(lb[j].y));
        t.z = __uint_as_float(f2tf(lb[j].z)); t.w = __uint_as_float(f2tf(lb[j].w));
        *(float4*)&Bs[(size_t)(bn + 32 * j) * ASTR + akc] = t;
    }
    __syncthreads();

    for (int it = 0; it < nIt; it++) {
        int buf = it & 1;
        // prefetch next tile into regs
        if (it + 1 < nIt) {
            int k0 = (it + 1) * TBK;
            #pragma unroll
            for (int j = 0; j < 4; j++)
                la[j] = *(const float4*)(Ab + (size_t)(m0 + am + 32 * j) * lda + k0 + akc);
            #pragma unroll
            for (int j = 0; j < 2; j++)
                lb[j] = *(const float4*)(Bb + (size_t)(n0 + bn + 32 * j) * ldb + k0 + akc);
        }
        // compute 4 k-steps of 8
        float* Asb = As + (size_t)buf * TBM * ASTR;
        float* Bsb = Bs + (size_t)buf * TBN * ASTR;
        #pragma unroll
        for (int ks = 0; ks < 4; ks++) {
            int k = ks * 8;
            unsigned afr[2][4], bfr[4][2];
            #pragma unroll
            for (int mt = 0; mt < 2; mt++) {
                int rb = wm * 32 + mt * 16 + grp;
                afr[mt][0] = __float_as_uint(Asb[rb * ASTR + k + tig]);
                afr[mt][1] = __float_as_uint(Asb[(rb + 8) * ASTR + k + tig]);
                afr[mt][2] = __float_as_uint(Asb[rb * ASTR + k + tig + 4]);
                afr[mt][3] = __float_as_uint(Asb[(rb + 8) * ASTR + k + tig + 4]);
            }
            #pragma unroll
            for (int nt = 0; nt < 4; nt++) {
                int cb = wn * 32 + nt * 8 + grp;
                bfr[nt][0] = __float_as_uint(Bsb[cb * ASTR + k + tig]);
                bfr[nt][1] = __float_as_uint(Bsb[cb * ASTR + k + tig + 4]);
            }
            #pragma unroll
            for (int mt = 0; mt < 2; mt++)
                #pragma unroll
                for (int nt = 0; nt < 4; nt++) {
                    asm volatile(
                        "mma.sync.aligned.m16n8k8.row.col.f32.tf32.tf32.f32 "
                        "{%0,%1,%2,%3}, {%4,%5,%6,%7}, {%8,%9}, {%0,%1,%2,%3};\n"
                        : "+f"(acc[mt][nt][0]), "+f"(acc[mt][nt][1]),
                          "+f"(acc[mt][nt][2]), "+f"(acc[mt][nt][3])
                        : "r"(afr[mt][0]), "r"(afr[mt][1]), "r"(afr[mt][2]), "r"(afr[mt][3]),
                          "r"(bfr[nt][0]), "r"(bfr[nt][1]));
                }
        }
        __syncthreads();
        if (it + 1 < nIt) {
            int nbuf = (it + 1) & 1;
            float* Asn = As + (size_t)nbuf * TBM * ASTR;
            float* Bsn = Bs + (size_t)nbuf * TBN * ASTR;
            #pragma unroll
            for (int j = 0; j < 4; j++) {
                float4 t; t.x = __uint_as_float(f2tf(la[j].x)); t.y = __uint_as_float(f2tf(la[j].y));
                t.z = __uint_as_float(f2tf(la[j].z)); t.w = __uint_as_float(f2tf(la[j].w));
                *(float4*)&Asn[(size_t)(am + 32 * j) * ASTR + akc] = t;
            }
            #pragma unroll
            for (int j = 0; j < 2; j++) {
                float4 t; t.x = __uint_as_float(f2tf(lb[j].x)); t.y = __uint_as_float(f2tf(lb[j].y));
                t.z = __uint_as_float(f2tf(lb[j].z)); t.w = __uint_as_float(f2tf(lb[j].w));
                *(float4*)&Bsn[(size_t)(bn + 32 * j) * ASTR + akc] = t;
            }
            __syncthreads();
        }
    }

    // epilogue
    #pragma unroll
    for (int mt = 0; mt < 2; mt++) {
        #pragma unroll
        for (int nt = 0; nt < 4; nt++) {
            int gn = n0 + wn * 32 + nt * 8 + tig * 2;
            float bv0 = biasb ? biasb[gn] : 0.f;
            float bv1 = biasb ? biasb[gn + 1] : 0.f;
            #pragma unroll
            for (int rh = 0; rh < 2; rh++) {
                int gm = m0 + wm * 32 + mt * 16 + grp + rh * 8;
                float v0 = acc[mt][nt][rh * 2 + 0] + bv0;
                float v1 = acc[mt][nt][rh * 2 + 1] + bv1;
                if (resid) {
                    v0 += resid[(size_t)gm * ldr + gn];
                    v1 += resid[(size_t)gm * ldr + gn + 1];
                }
                if (relu) { v0 = fmaxf(v0, 0.f); v1 = fmaxf(v1, 0.f); }
                float2 o; o.x = v0; o.y = v1;
                *(float2*)(Cb + (size_t)gm * ldc + gn) = o;
            }
        }
    }
}

// ---------------- LayerNorm (optionally masked by span length) --------------
__global__ __launch_bounds__(256) void ln_kernel(
    const float* __restrict__ in, const float* __restrict__ gamma,
    const float* __restrict__ beta, const int* __restrict__ ids,
    float* __restrict__ out)
{
    __shared__ float red1[8], red2[8];
    __shared__ float bc1, bc2;
    int row = blockIdx.x, tid = threadIdx.x;
    const float* x = in + (size_t)row * PH;

    float v[3];
    #pragma unroll
    for (int j = 0; j < 3; j++) v[j] = x[tid + j * 256];

    float s = v[0] + v[1] + v[2];
    #pragma unroll
    for (int o = 16; o; o >>= 1) s += __shfl_xor_sync(0xffffffffu, s, o);
    if ((tid & 31) == 0) red1[tid >> 5] = s;
    __syncthreads();
    if (tid < 8) {
        float t = red1[tid];
        #pragma unroll
        for (int o = 4; o; o >>= 1) t += __shfl_xor_sync(0xffu, t, o);
        if (!tid) bc1 = t;
    }
    __syncthreads();
    float mu = bc1 * (1.0f / PH);

    float d0 = v[0] - mu, d1 = v[1] - mu, d2 = v[2] - mu;
    float sq = d0 * d0 + d1 * d1 + d2 * d2;
    #pragma unroll
    for (int o = 16; o; o >>= 1) sq += __shfl_xor_sync(0xffffffffu, sq, o);
    if ((tid & 31) == 0) red2[tid >> 5] = sq;
    __syncthreads();
    if (tid < 8) {
        float t = red2[tid];
        #pragma unroll
        for (int o = 4; o; o >>= 1) t += __shfl_xor_sync(0xffu, t, o);
        if (!tid) bc2 = t;
    }
    __syncthreads();
    float var = bc2 * (1.0f / PH);
    float rs = rsqrtf(var + 1e-5f);

    float mask = 1.0f;
    if (ids) {
        int a = ids[2 * row], b = ids[2 * row + 1];
        if (b - a <= 0) mask = 0.f;
    }
    #pragma unroll
    for (int j = 0; j < 3; j++) {
        int c = tid + j * 256;
        out[(size_t)row * PH + c] = ((v[j] - mu) * rs * gamma[c] + beta[c]) * mask;
    }
}

// ---------------- launch -----------------------------------------------------
extern "C" void kernel_launch(void* const* d_in, const int* in_sizes, int n_in,
                              void* d_out, int out_size) {
    const float* tok = (const float*)d_in[0];
    const int*   ids = (const int*)d_in[1];     // int32 (JAX x64 disabled)
    const float* q0  = (const float*)d_in[2];
    const float* inw = (const float*)d_in[3];
    const float* inb = (const float*)d_in[4];
    const float* ow  = (const float*)d_in[5];
    const float* ob  = (const float*)d_in[6];
    const float* lng = (const float*)d_in[7];
    const float* lnb = (const float*)d_in[8];
    const float* w1  = (const float*)d_in[9];
    const float* b1  = (const float*)d_in[10];
    const float* w2  = (const float*)d_in[11];
    const float* b2  = (const float*)d_in[12];
    float* out = (float*)d_out;

    float *p_p, *p_ctx, *p_att, *p_x1, *p_h, *p_z;
    cudaGetSymbolAddress((void**)&p_p,   g_p);
    cudaGetSymbolAddress((void**)&p_ctx, g_ctx);
    cudaGetSymbolAddress((void**)&p_att, g_att);
    cudaGetSymbolAddress((void**)&p_x1,  g_x1);
    cudaGetSymbolAddress((void**)&p_h,   g_hmid);
    cudaGetSymbolAddress((void**)&p_z,   g_z);

    cudaFuncSetAttribute(gemm_tf32_kernel,
                         cudaFuncAttributeMaxDynamicSharedMemorySize, SMEM_GEMM);

    // K0: tok+pe, projections, T table
    tokpe_kernel<<<PB * PSL, 256>>>(tok);
    qproj_kernel<<<96, 256>>>(inw, inb, q0);
    uprep_kernel<<<36, 256>>>(inw, inb);
    tproj_kernel<<<PB * PSL / 4, 128>>>();

    // K1: per-span scores/softmax/pooling
    span_kernel<<<PN, 192>>>(ids);

    // K2: ctx = p @ Wv^T + bv (batched over heads)
    gemm_tf32_kernel<<<dim3(1, PN / TBM, PNH), 256, SMEM_GEMM>>>(
        p_p, inw + (size_t)2 * PH * PH, inb + 2 * PH, (const float*)0, p_ctx,
        PH, PH, PH, PH, 0,
        (long long)PN * PH, (long long)PHD * PH, PHD, PHD, 0);

    // K3: attn_out = ctx @ O^T + ob + q0(broadcast)
    gemm_tf32_kernel<<<dim3(PH / TBN, PN / TBM, 1), 256, SMEM_GEMM>>>(
        p_ctx, ow, ob, q0, p_att,
        PH, PH, PH, PH, 0, 0, 0, 0, 0, 0);

    // K4: x1 = LN(attn_out)
    ln_kernel<<<PN, 256>>>(p_att, lng, lnb, (const int*)0, p_x1);

    // K5: h = relu(x1 @ W1^T + b1)
    gemm_tf32_kernel<<<dim3(PFFN / TBN, PN / TBM, 1), 256, SMEM_GEMM>>>(
        p_x1, w1, b1, (const float*)0, p_h,
        PH, PH, PH, PFFN, 0, 0, 0, 0, 0, 1);

    // K6: z = h @ W2^T + b2 + x1
    gemm_tf32_kernel<<<dim3(PH / TBN, PN / TBM, 1), 256, SMEM_GEMM>>>(
        p_h, w2, b2, p_x1, p_z,
        PFFN, PFFN, PFFN, PH, PH, 0, 0, 0, 0, 0);

    // K7: out = LN(z) masked by length>0
    ln_kernel<<<PN, 256>>>(p_z, lng, lnb, ids, out);
}

// round 6
// speedup vs baseline: 3.9522x; 1.2586x over previous
#include <cuda_runtime.h>
#include <cuda_fp16.h>
#include <math.h>
#include <stdint.h>

// Problem constants
#define PB   8
#define PSL  512
#define PH   768
#define PNS  256
#define PW   32
#define PNH  12
#define PHD  64
#define PFFN 3072
#define PN   2048   // B*NS

// ---------------- scratch (device globals) ----------------------------------
__device__ float  g_tokpe[PB * PSL * PH];
__device__ float  g_qproj[PH];
__device__ float  g_u[PNH * PH];
__device__ float  g_c[PNH];
__device__ float  g_T[PB * PSL * PNH];
__device__ __half g_p16[(size_t)PNH * PN * PH];
__device__ __half g_ctx16[(size_t)PN * PH];
__device__ float  g_att[(size_t)PN * PH];
__device__ float  g_x1[(size_t)PN * PH];
__device__ __half g_x116[(size_t)PN * PH];
__device__ __half g_h16[(size_t)PN * PFFN];
__device__ float  g_z[(size_t)PN * PH];
// fp16 weights
__device__ __half g_wv16[PH * PH];
__device__ __half g_wo16[PH * PH];
__device__ __half g_w116[PFFN * PH];
__device__ __half g_w216[PH * PFFN];

// ---------------- helpers ----------------------------------------------------
__device__ __forceinline__ uint32_t smem_u32(const void* p) {
    uint32_t a;
    asm("{ .reg .u64 t; cvta.to.shared.u64 t, %1; cvt.u32.u64 %0, t; }" : "=r"(a) : "l"(p));
    return a;
}

// ---------------- K0a: tok + PE ---------------------------------------------
__global__ void tokpe_kernel(const float* __restrict__ tok) {
    int r = blockIdx.x;
    int pos = r % PSL;
    size_t base = (size_t)r * PH;
    for (int c = threadIdx.x; c < PH; c += blockDim.x) {
        int i2 = (c >> 1) * 2;
        float div = expf((float)i2 * (-9.210340371976184f / (float)PH));
        float ang = (float)pos * div;
        float pe = (c & 1) ? cosf(ang) : sinf(ang);
        g_tokpe[base + c] = tok[base + c] + pe;
    }
}

// ---------------- K0b: q projection -----------------------------------------
__global__ void qproj_kernel(const float* __restrict__ w, const float* __restrict__ b,
                             const float* __restrict__ q0) {
    int gt = blockIdx.x * blockDim.x + threadIdx.x;
    int warp = gt >> 5, lane = gt & 31;
    if (warp >= PH) return;
    const float* wr = w + (size_t)warp * PH;
    float acc = 0.f;
    for (int e = lane; e < PH; e += 32) acc += wr[e] * q0[e];
    #pragma unroll
    for (int o = 16; o; o >>= 1) acc += __shfl_xor_sync(0xffffffffu, acc, o);
    if (!lane) g_qproj[warp] = acc + b[warp];
}

// ---------------- K0c: u_h, c_h ---------------------------------------------
__global__ void uprep_kernel(const float* __restrict__ w, const float* __restrict__ b) {
    int idx = blockIdx.x * blockDim.x + threadIdx.x;
    if (idx < PNH * PH) {
        int h = idx / PH, e = idx % PH;
        float acc = 0.f;
        #pragma unroll 8
        for (int d = 0; d < PHD; d++)
            acc += w[((size_t)(PH + h * PHD + d)) * PH + e] * g_qproj[h * PHD + d];
        g_u[idx] = acc;
    }
    if (idx < PNH) {
        float acc = 0.f;
        #pragma unroll 8
        for (int d = 0; d < PHD; d++)
            acc += g_qproj[idx * PHD + d] * b[PH + idx * PHD + d];
        g_c[idx] = acc;
    }
}

// ---------------- K0e: f32 -> f16 weight conversion --------------------------
__global__ void f2h_kernel(const float* __restrict__ s, __half* __restrict__ d, int n) {
    for (int i = blockIdx.x * blockDim.x + threadIdx.x; i < n; i += gridDim.x * blockDim.x)
        d[i] = __float2half_rn(s[i]);
}

// ---------------- K0d: T[b,pos,h] = tokpe[b,pos] . u_h ----------------------
__global__ __launch_bounds__(128) void tproj_kernel() {
    int row  = blockIdx.x * 4 + (threadIdx.x >> 5);
    int lane = threadIdx.x & 31;
    const float4* rp = (const float4*)g_tokpe + (size_t)row * (PH / 4);
    float4 rr[6];
    #pragma unroll
    for (int j = 0; j < 6; j++) rr[j] = rp[lane + 32 * j];
    #pragma unroll
    for (int h = 0; h < PNH; h++) {
        const float4* up = (const float4*)g_u + h * (PH / 4);
        float acc = 0.f;
        #pragma unroll
        for (int j = 0; j < 6; j++) {
            float4 u4 = __ldg(up + lane + 32 * j);
            acc += rr[j].x * u4.x + rr[j].y * u4.y + rr[j].z * u4.z + rr[j].w * u4.w;
        }
        #pragma unroll
        for (int o = 16; o; o >>= 1) acc += __shfl_xor_sync(0xffffffffu, acc, o);
        if (!lane) g_T[row * PNH + h] = acc;
    }
}

// ---------------- K1: span scores + softmax + pooling (emit fp16 p) ---------
__global__ __launch_bounds__(192) void span_kernel(const int* __restrict__ ids) {
    __shared__ float s_att[PNH * PW];
    int n = blockIdx.x;
    int b = n >> 8;
    int tid = threadIdx.x;
    int start = ids[2 * n];
    int len   = ids[2 * n + 1] - start;

    for (int i = tid; i < PNH * PW; i += 192) {
        int h = i >> 5, w = i & 31;
        float v = -1e9f;
        if (w < len)
            v = (g_T[(b * PSL + start + w) * PNH + h] + g_c[h]) * 0.125f;
        s_att[h * PW + w] = v;
    }
    __syncthreads();

    int warp = tid >> 5, lane = tid & 31;
    for (int h = warp; h < PNH; h += 6) {
        float v = s_att[h * PW + lane];
        float mx = v;
        #pragma unroll
        for (int o = 16; o; o >>= 1) mx = fmaxf(mx, __shfl_xor_sync(0xffffffffu, mx, o));
        float e = __expf(v - mx);
        float s = e;
        #pragma unroll
        for (int o = 16; o; o >>= 1) s += __shfl_xor_sync(0xffffffffu, s, o);
        s_att[h * PW + lane] = e / s;
    }
    __syncthreads();

    const float4* base = (const float4*)g_tokpe + ((size_t)(b * PSL + start)) * (PH / 4);
    float4 acc[PNH];
    #pragma unroll
    for (int h = 0; h < PNH; h++) acc[h] = make_float4(0.f, 0.f, 0.f, 0.f);
    #pragma unroll 4
    for (int w = 0; w < PW; w++) {
        float4 v = base[(size_t)w * (PH / 4) + tid];
        #pragma unroll
        for (int h = 0; h < PNH; h++) {
            float a = s_att[h * PW + w];
            acc[h].x += a * v.x; acc[h].y += a * v.y;
            acc[h].z += a * v.z; acc[h].w += a * v.w;
        }
    }
    #pragma unroll
    for (int h = 0; h < PNH; h++) {
        size_t o2 = (((size_t)h * PN + n) * PH) / 2 + tid * 2;
        ((half2*)g_p16)[o2 + 0] = __floats2half2_rn(acc[h].x, acc[h].y);
        ((half2*)g_p16)[o2 + 1] = __floats2half2_rn(acc[h].z, acc[h].w);
    }
}

// ---------------- fp16 mma.sync GEMM: C = A @ B^T (+bias)(+resid)(relu) -----
// Tile 128(M) x TBN(N) x 64(K halves) per stage, 3-stage cp.async pipeline.
// 256 threads = 8 warps. Row stride in smem: 72 halves (144B) -> conflict-free frags.
#define TCM 128
#define KHC 64        // K halves per stage
#define RSTR 72       // padded row stride (halves)

template<int TBN>
__global__ __launch_bounds__(256) void gemm_h_kernel(
    const __half* __restrict__ A, const __half* __restrict__ Bm,
    const float* __restrict__ bias, const float* __restrict__ resid,
    float* __restrict__ Cf, __half* __restrict__ Ch,
    int K, int lda, int ldb, int ldc, int ldr,
    long long sA, long long sB, long long sC, long long sBias, int relu)
{
    constexpr int WNW = TBN / 32;          // warps along N
    constexpr int WMW = 8 / WNW;           // warps along M
    constexpr int WTM = TCM / WMW;         // rows per warp
    constexpr int MT  = WTM / 16;          // m16 tiles per warp
    constexpr int BCH = TBN * 8 / 256;     // B cp.async chunks per thread
    constexpr int TPRB = 8 / BCH;          // threads per B row
    constexpr int STAGEH = (TCM + TBN) * RSTR;   // halves per stage

    extern __shared__ __half smh[];

    int z = blockIdx.z;
    const __half* Ab = A + (size_t)z * sA;
    const __half* Bb = Bm + (size_t)z * sB;
    float* Cfb = Cf ? Cf + (size_t)z * sC : (float*)0;
    __half* Chb = Ch ? Ch + (size_t)z * sC : (__half*)0;
    const float* biasb = bias ? bias + (size_t)z * sBias : (const float*)0;

    int m0 = blockIdx.y * TCM;
    int n0 = blockIdx.x * TBN;
    int tid = threadIdx.x;
    int warp = tid >> 5, lane = tid & 31;
    int grp = lane >> 2, tig = lane & 3;
    int wn = warp % WNW, wm = warp / WNW;

    float acc[MT][4][4];
    #pragma unroll
    for (int mt = 0; mt < MT; mt++)
        #pragma unroll
        for (int nt = 0; nt < 4; nt++)
            #pragma unroll
            for (int r = 0; r < 4; r++) acc[mt][nt][r] = 0.f;

    // cp.async indices
    int arow = tid >> 1;                 // A: 2 threads/row, 4 chunks each
    int acb  = (tid & 1) * 4;            // chunk base (16B units)
    int brow = tid / TPRB;               // B row
    int bcb  = (tid % TPRB) * BCH;

    int nSt = K / KHC;

    // issue one stage of cp.async
    auto issue = [&](int s, int buf) {
        int k0 = s * KHC;
        uint32_t sa = smem_u32(smh + (size_t)buf * STAGEH);
        uint32_t sbb = sa + TCM * RSTR * 2;
        const __half* asrc = Ab + (size_t)(m0 + arow) * lda + k0;
        uint32_t adst = sa + (arow * RSTR) * 2;
        #pragma unroll
        for (int j = 0; j < 4; j++) {
            int c = acb + j;
            asm volatile("cp.async.cg.shared.global [%0], [%1], 16;"
                         :: "r"(adst + c * 16), "l"(asrc + c * 8) : "memory");
        }
        const __half* bsrc = Bb + (size_t)(n0 + brow) * ldb + k0;
        uint32_t bdst = sbb + (brow * RSTR) * 2;
        #pragma unroll
        for (int j = 0; j < BCH; j++) {
            int c = bcb + j;
            asm volatile("cp.async.cg.shared.global [%0], [%1], 16;"
                         :: "r"(bdst + c * 16), "l"(bsrc + c * 8) : "memory");
        }
    };

    // prologue: stages 0,1
    issue(0, 0);
    asm volatile("cp.async.commit_group;" ::: "memory");
    issue(1, 1);
    asm volatile("cp.async.commit_group;" ::: "memory");

    for (int s = 0; s < nSt; s++) {
        asm volatile("cp.async.wait_group 1;" ::: "memory");
        __syncthreads();
        if (s + 2 < nSt) issue(s + 2, (s + 2) % 3);
        asm volatile("cp.async.commit_group;" ::: "memory");

        const __half* As = smh + (size_t)(s % 3) * STAGEH;
        const __half* Bs = As + TCM * RSTR;
        #pragma unroll
        for (int kk = 0; kk < 4; kk++) {
            int k = kk * 16;
            uint32_t af[MT][4], bf[4][2];
            #pragma unroll
            for (int mt = 0; mt < MT; mt++) {
                int rb = wm * WTM + mt * 16 + grp;
                af[mt][0] = *(const uint32_t*)(As + rb * RSTR + k + 2 * tig);
                af[mt][1] = *(const uint32_t*)(As + (rb + 8) * RSTR + k + 2 * tig);
                af[mt][2] = *(const uint32_t*)(As + rb * RSTR + k + 8 + 2 * tig);
                af[mt][3] = *(const uint32_t*)(As + (rb + 8) * RSTR + k + 8 + 2 * tig);
            }
            #pragma unroll
            for (int nt = 0; nt < 4; nt++) {
                int cb = wn * 32 + nt * 8 + grp;
                bf[nt][0] = *(const uint32_t*)(Bs + cb * RSTR + k + 2 * tig);
                bf[nt][1] = *(const uint32_t*)(Bs + cb * RSTR + k + 8 + 2 * tig);
            }
            #pragma unroll
            for (int mt = 0; mt < MT; mt++)
                #pragma unroll
                for (int nt = 0; nt < 4; nt++) {
                    asm volatile(
                        "mma.sync.aligned.m16n8k16.row.col.f32.f16.f16.f32 "
                        "{%0,%1,%2,%3}, {%4,%5,%6,%7}, {%8,%9}, {%0,%1,%2,%3};"
                        : "+f"(acc[mt][nt][0]), "+f"(acc[mt][nt][1]),
                          "+f"(acc[mt][nt][2]), "+f"(acc[mt][nt][3])
                        : "r"(af[mt][0]), "r"(af[mt][1]), "r"(af[mt][2]), "r"(af[mt][3]),
                          "r"(bf[nt][0]), "r"(bf[nt][1]));
                }
        }
        __syncthreads();
    }

    // epilogue
    #pragma unroll
    for (int mt = 0; mt < MT; mt++) {
        #pragma unroll
        for (int nt = 0; nt < 4; nt++) {
            int gn = n0 + wn * 32 + nt * 8 + tig * 2;
            float bv0 = biasb ? biasb[gn] : 0.f;
            float bv1 = biasb ? biasb[gn + 1] : 0.f;
            #pragma unroll
            for (int rh = 0; rh < 2; rh++) {
                int gm = m0 + wm * WTM + mt * 16 + grp + rh * 8;
                float v0 = acc[mt][nt][rh * 2 + 0] + bv0;
                float v1 = acc[mt][nt][rh * 2 + 1] + bv1;
                if (resid) {
                    v0 += resid[(size_t)gm * ldr + gn];
                    v1 += resid[(size_t)gm * ldr + gn + 1];
                }
                if (relu) { v0 = fmaxf(v0, 0.f); v1 = fmaxf(v1, 0.f); }
                if (Cfb) {
                    float2 o; o.x = v0; o.y = v1;
                    *(float2*)(Cfb + (size_t)gm * ldc + gn) = o;
                }
                if (Chb)
                    *(half2*)(Chb + (size_t)gm * ldc + gn) = __floats2half2_rn(v0, v1);
            }
        }
    }
}

// ---------------- LayerNorm (optional mask, optional fp16 copy) -------------
__global__ __launch_bounds__(256) void ln_kernel(
    const float* __restrict__ in, const float* __restrict__ gamma,
    const float* __restrict__ beta, const int* __restrict__ ids,
    float* __restrict__ out, __half* __restrict__ out16)
{
    __shared__ float red1[8], red2[8];
    __shared__ float bc1, bc2;
    int row = blockIdx.x, tid = threadIdx.x;
    const float* x = in + (size_t)row * PH;

    float v[3];
    #pragma unroll
    for (int j = 0; j < 3; j++) v[j] = x[tid + j * 256];

    float s = v[0] + v[1] + v[2];
    #pragma unroll
    for (int o = 16; o; o >>= 1) s += __shfl_xor_sync(0xffffffffu, s, o);
    if ((tid & 31) == 0) red1[tid >> 5] = s;
    __syncthreads();
    if (tid < 8) {
        float t = red1[tid];
        #pragma unroll
        for (int o = 4; o; o >>= 1) t += __shfl_xor_sync(0xffu, t, o);
        if (!tid) bc1 = t;
    }
    __syncthreads();
    float mu = bc1 * (1.0f / PH);

    float d0 = v[0] - mu, d1 = v[1] - mu, d2 = v[2] - mu;
    float sq = d0 * d0 + d1 * d1 + d2 * d2;
    #pragma unroll
    for (int o = 16; o; o >>= 1) sq += __shfl_xor_sync(0xffffffffu, sq, o);
    if ((tid & 31) == 0) red2[tid >> 5] = sq;
    __syncthreads();
    if (tid < 8) {
        float t = red2[tid];
        #pragma unroll
        for (int o = 4; o; o >>= 1) t += __shfl_xor_sync(0xffu, t, o);
        if (!tid) bc2 = t;
    }
    __syncthreads();
    float var = bc2 * (1.0f / PH);
    float rs = rsqrtf(var + 1e-5f);

    float mask = 1.0f;
    if (ids) {
        int a = ids[2 * row], b = ids[2 * row + 1];
        if (b - a <= 0) mask = 0.f;
    }
    #pragma unroll
    for (int j = 0; j < 3; j++) {
        int c = tid + j * 256;
        float o = ((v[j] - mu) * rs * gamma[c] + beta[c]) * mask;
        out[(size_t)row * PH + c] = o;
        if (out16) out16[(size_t)row * PH + c] = __float2half_rn(o);
    }
}

// ---------------- launch -----------------------------------------------------
#define SMEM_G128 (3 * (TCM + 128) * RSTR * 2)
#define SMEM_G64  (3 * (TCM + 64) * RSTR * 2)

extern "C" void kernel_launch(void* const* d_in, const int* in_sizes, int n_in,
                              void* d_out, int out_size) {
    const float* tok = (const float*)d_in[0];
    const int*   ids = (const int*)d_in[1];
    const float* q0  = (const float*)d_in[2];
    const float* inw = (const float*)d_in[3];
    const float* inb = (const float*)d_in[4];
    const float* ow  = (const float*)d_in[5];
    const float* ob  = (const float*)d_in[6];
    const float* lng = (const float*)d_in[7];
    const float* lnb = (const float*)d_in[8];
    const float* w1  = (const float*)d_in[9];
    const float* b1  = (const float*)d_in[10];
    const float* w2  = (const float*)d_in[11];
    const float* b2  = (const float*)d_in[12];
    float* out = (float*)d_out;

    __half *p_p16, *p_ctx16, *p_x116, *p_h16, *p_wv16, *p_wo16, *p_w116, *p_w216;
    float *p_att, *p_x1, *p_z;
    cudaGetSymbolAddress((void**)&p_p16,   g_p16);
    cudaGetSymbolAddress((void**)&p_ctx16, g_ctx16);
    cudaGetSymbolAddress((void**)&p_att,   g_att);
    cudaGetSymbolAddress((void**)&p_x1,    g_x1);
    cudaGetSymbolAddress((void**)&p_x116,  g_x116);
    cudaGetSymbolAddress((void**)&p_h16,   g_h16);
    cudaGetSymbolAddress((void**)&p_z,     g_z);
    cudaGetSymbolAddress((void**)&p_wv16,  g_wv16);
    cudaGetSymbolAddress((void**)&p_wo16,  g_wo16);
    cudaGetSymbolAddress((void**)&p_w116,  g_w116);
    cudaGetSymbolAddress((void**)&p_w216,  g_w216);

    cudaFuncSetAttribute(gemm_h_kernel<128>,
                         cudaFuncAttributeMaxDynamicSharedMemorySize, SMEM_G128);
    cudaFuncSetAttribute(gemm_h_kernel<64>,
                         cudaFuncAttributeMaxDynamicSharedMemorySize, SMEM_G64);

    // K0: prep
    tokpe_kernel<<<PB * PSL, 256>>>(tok);
    qproj_kernel<<<96, 256>>>(inw, inb, q0);
    uprep_kernel<<<36, 256>>>(inw, inb);
    tproj_kernel<<<PB * PSL / 4, 128>>>();
    f2h_kernel<<<256, 256>>>(inw + (size_t)2 * PH * PH, p_wv16, PH * PH);
    f2h_kernel<<<256, 256>>>(ow, p_wo16, PH * PH);
    f2h_kernel<<<512, 256>>>(w1, p_w116, PFFN * PH);
    f2h_kernel<<<512, 256>>>(w2, p_w216, PH * PFFN);

    // K1: per-span scores/softmax/pooling -> p16
    span_kernel<<<PN, 192>>>(ids);

    // K2: ctx16 = p @ Wv^T + bv (batched over heads), N=64 per head
    gemm_h_kernel<64><<<dim3(1, PN / TCM, PNH), 256, SMEM_G64>>>(
        p_p16, p_wv16, inb + 2 * PH, (const float*)0, (float*)0, p_ctx16,
        PH, PH, PH, PH, 0,
        (long long)PN * PH, (long long)PHD * PH, PHD, PHD, 0);

    // K3: att = ctx @ O^T + ob + q0(broadcast)
    gemm_h_kernel<128><<<dim3(PH / 128, PN / TCM, 1), 256, SMEM_G128>>>(
        p_ctx16, p_wo16, ob, q0, p_att, (__half*)0,
        PH, PH, PH, PH, 0, 0, 0, 0, 0, 0);

    // K4: x1 = LN(att); also x116
    ln_kernel<<<PN, 256>>>(p_att, lng, lnb, (const int*)0, p_x1, p_x116);

    // K5: h16 = relu(x1 @ W1^T + b1)
    gemm_h_kernel<128><<<dim3(PFFN / 128, PN / TCM, 1), 256, SMEM_G128>>>(
        p_x116, p_w116, b1, (const float*)0, (float*)0, p_h16,
        PH, PH, PH, PFFN, 0, 0, 0, 0, 0, 1);

    // K6: z = h @ W2^T + b2 + x1
    gemm_h_kernel<128><<<dim3(PH / 128, PN / TCM, 1), 256, SMEM_G128>>>(
        p_h16, p_w216, b2, p_x1, p_z, (__half*)0,
        PFFN, PFFN, PFFN, PH, PH, 0, 0, 0, 0, 0);

    // K7: out = LN(z) masked by length>0
    ln_kernel<<<PN, 256>>>(p_z, lng, lnb, ids, out, (__half*)0);
}

// round 7
// speedup vs baseline: 4.5565x; 1.1529x over previous
#include <cuda_runtime.h>
#include <cuda_fp16.h>
#include <math.h>
#include <stdint.h>

// Problem constants
#define PB   8
#define PSL  512
#define PH   768
#define PNS  256
#define PW   32
#define PNH  12
#define PHD  64
#define PFFN 3072
#define PN   2048   // B*NS

// ---------------- scratch (device globals) ----------------------------------
__device__ float  g_tokpe[PB * PSL * PH];
__device__ float  g_qproj[PH];
__device__ float  g_u[PNH * PH];
__device__ float  g_c[PNH];
__device__ float  g_T[PB * PSL * PNH];
__device__ __half g_p16[(size_t)PNH * PN * PH];
__device__ __half g_ctx16[(size_t)PN * PH];
__device__ float  g_att[(size_t)PN * PH];
__device__ float  g_x1[(size_t)PN * PH];
__device__ __half g_x116[(size_t)PN * PH];
__device__ __half g_h16[(size_t)PN * PFFN];
__device__ float  g_z[(size_t)PN * PH];
// fp16 weights
__device__ __half g_wv16[PH * PH];
__device__ __half g_wo16[PH * PH];
__device__ __half g_w116[PFFN * PH];
__device__ __half g_w216[PH * PFFN];

// ---------------- helpers ----------------------------------------------------
__device__ __forceinline__ uint32_t smem_u32(const void* p) {
    uint32_t a;
    asm("{ .reg .u64 t; cvta.to.shared.u64 t, %1; cvt.u32.u64 %0, t; }" : "=r"(a) : "l"(p));
    return a;
}

// ---------------- K0b: q projection -----------------------------------------
__global__ void qproj_kernel(const float* __restrict__ w, const float* __restrict__ b,
                             const float* __restrict__ q0) {
    int gt = blockIdx.x * blockDim.x + threadIdx.x;
    int warp = gt >> 5, lane = gt & 31;
    if (warp >= PH) return;
    const float* wr = w + (size_t)warp * PH;
    float acc = 0.f;
    for (int e = lane; e < PH; e += 32) acc += wr[e] * q0[e];
    #pragma unroll
    for (int o = 16; o; o >>= 1) acc += __shfl_xor_sync(0xffffffffu, acc, o);
    if (!lane) g_qproj[warp] = acc + b[warp];
}

// ---------------- K0c: u_h, c_h ---------------------------------------------
__global__ void uprep_kernel(const float* __restrict__ w, const float* __restrict__ b) {
    int idx = blockIdx.x * blockDim.x + threadIdx.x;
    if (idx < PNH * PH) {
        int h = idx / PH, e = idx % PH;
        float acc = 0.f;
        #pragma unroll 8
        for (int d = 0; d < PHD; d++)
            acc += w[((size_t)(PH + h * PHD + d)) * PH + e] * g_qproj[h * PHD + d];
        g_u[idx] = acc;
    }
    if (idx < PNH) {
        float acc = 0.f;
        #pragma unroll 8
        for (int d = 0; d < PHD; d++)
            acc += g_qproj[idx * PHD + d] * b[PH + idx * PHD + d];
        g_c[idx] = acc;
    }
}

// ---------------- K0e: merged f32 -> f16 weight conversion -------------------
__global__ void f2h4_kernel(const float* s0, __half* d0, int n0,
                            const float* s1, __half* d1, int n1,
                            const float* s2, __half* d2, int n2,
                            const float* s3, __half* d3, int n3) {
    const float* s; __half* d; int n;
    switch (blockIdx.y) {
        case 0: s = s0; d = d0; n = n0; break;
        case 1: s = s1; d = d1; n = n1; break;
        case 2: s = s2; d = d2; n = n2; break;
        default: s = s3; d = d3; n = n3; break;
    }
    for (int i = blockIdx.x * blockDim.x + threadIdx.x; i * 2 < n;
         i += gridDim.x * blockDim.x) {
        float2 v = *(const float2*)(s + i * 2);
        ((half2*)d)[i] = __floats2half2_rn(v.x, v.y);
    }
}

// ---------------- K0: fused tok+PE and T projection --------------------------
// One warp per row: builds tokpe row in registers, writes it, then dots with u.
__global__ __launch_bounds__(128) void tokpe_tproj_kernel(const float* __restrict__ tok) {
    int row  = blockIdx.x * 4 + (threadIdx.x >> 5);   // 0..4095
    int lane = threadIdx.x & 31;
    int pos  = row % PSL;
    const float kexp = -9.210340371976184f / (float)PH;
    const float4* tp = (const float4*)tok + (size_t)row * (PH / 4);
    float4* op = (float4*)g_tokpe + (size_t)row * (PH / 4);

    float4 rr[6];
    #pragma unroll
    for (int j = 0; j < 6; j++) {
        int c4 = lane + 32 * j;          // float4 index; columns 4*c4 .. 4*c4+3
        float4 v = tp[c4];
        float d0 = expf((float)(4 * c4) * kexp);
        float d1 = expf((float)(4 * c4 + 2) * kexp);
        float a0 = (float)pos * d0, a1 = (float)pos * d1;
        v.x += sinf(a0); v.y += cosf(a0);
        v.z += sinf(a1); v.w += cosf(a1);
        rr[j] = v;
        op[c4] = v;
    }
    #pragma unroll
    for (int h = 0; h < PNH; h++) {
        const float4* up = (const float4*)g_u + h * (PH / 4);
        float acc = 0.f;
        #pragma unroll
        for (int j = 0; j < 6; j++) {
            float4 u4 = __ldg(up + lane + 32 * j);
            acc += rr[j].x * u4.x + rr[j].y * u4.y + rr[j].z * u4.z + rr[j].w * u4.w;
        }
        #pragma unroll
        for (int o = 16; o; o >>= 1) acc += __shfl_xor_sync(0xffffffffu, acc, o);
        if (!lane) g_T[row * PNH + h] = acc;
    }
}

// ---------------- K1: span scores + softmax + pooling (emit fp16 p) ---------
__global__ __launch_bounds__(192) void span_kernel(const int* __restrict__ ids) {
    __shared__ float s_att[PNH * PW];
    int n = blockIdx.x;
    int b = n >> 8;
    int tid = threadIdx.x;
    int start = ids[2 * n];
    int len   = ids[2 * n + 1] - start;

    for (int i = tid; i < PNH * PW; i += 192) {
        int h = i >> 5, w = i & 31;
        float v = -1e9f;
        if (w < len)
            v = (g_T[(b * PSL + start + w) * PNH + h] + g_c[h]) * 0.125f;
        s_att[h * PW + w] = v;
    }
    __syncthreads();

    int warp = tid >> 5, lane = tid & 31;
    for (int h = warp; h < PNH; h += 6) {
        float v = s_att[h * PW + lane];
        float mx = v;
        #pragma unroll
        for (int o = 16; o; o >>= 1) mx = fmaxf(mx, __shfl_xor_sync(0xffffffffu, mx, o));
        float e = __expf(v - mx);
        float s = e;
        #pragma unroll
        for (int o = 16; o; o >>= 1) s += __shfl_xor_sync(0xffffffffu, s, o);
        s_att[h * PW + lane] = e / s;
    }
    __syncthreads();

    const float4* base = (const float4*)g_tokpe + ((size_t)(b * PSL + start)) * (PH / 4);
    float4 acc[PNH];
    #pragma unroll
    for (int h = 0; h < PNH; h++) acc[h] = make_float4(0.f, 0.f, 0.f, 0.f);
    #pragma unroll 4
    for (int w = 0; w < PW; w++) {
        float4 v = base[(size_t)w * (PH / 4) + tid];
        #pragma unroll
        for (int h = 0; h < PNH; h++) {
            float a = s_att[h * PW + w];
            acc[h].x += a * v.x; acc[h].y += a * v.y;
            acc[h].z += a * v.z; acc[h].w += a * v.w;
        }
    }
    #pragma unroll
    for (int h = 0; h < PNH; h++) {
        size_t o2 = (((size_t)h * PN + n) * PH) / 2 + tid * 2;
        ((half2*)g_p16)[o2 + 0] = __floats2half2_rn(acc[h].x, acc[h].y);
        ((half2*)g_p16)[o2 + 1] = __floats2half2_rn(acc[h].z, acc[h].w);
    }
}

// ---------------- fp16 mma.sync GEMM: C = A @ B^T (+bias)(+resid)(relu) -----
// Tile 128(M) x TBN(N) x 64(K halves) per stage, 3-stage cp.async pipeline.
// 256 threads = 8 warps. Smem rows padded to 72 halves; ldmatrix fragments.
#define TCM 128
#define KHC 64
#define RSTR 72

template<int TBN>
__global__ __launch_bounds__(256) void gemm_h_kernel(
    const __half* __restrict__ A, const __half* __restrict__ Bm,
    const float* __restrict__ bias, const float* __restrict__ resid,
    float* __restrict__ Cf, __half* __restrict__ Ch,
    int K, int lda, int ldb, int ldc, int ldr,
    long long sA, long long sB, long long sC, long long sBias, int relu)
{
    constexpr int WNW = TBN / 32;
    constexpr int WMW = 8 / WNW;
    constexpr int WTM = TCM / WMW;
    constexpr int MT  = WTM / 16;
    constexpr int BCH = TBN * 8 / 256;
    constexpr int TPRB = 8 / BCH;
    constexpr int STAGEH = (TCM + TBN) * RSTR;

    extern __shared__ __half smh[];

    int z = blockIdx.z;
    const __half* Ab = A + (size_t)z * sA;
    const __half* Bb = Bm + (size_t)z * sB;
    float* Cfb = Cf ? Cf + (size_t)z * sC : (float*)0;
    __half* Chb = Ch ? Ch + (size_t)z * sC : (__half*)0;
    const float* biasb = bias ? bias + (size_t)z * sBias : (const float*)0;

    int m0 = blockIdx.y * TCM;
    int n0 = blockIdx.x * TBN;
    int tid = threadIdx.x;
    int warp = tid >> 5, lane = tid & 31;
    int grp = lane >> 2, tig = lane & 3;
    int wn = warp % WNW, wm = warp / WNW;

    // ldmatrix lane offsets (bytes)
    // A x4: mat = lane>>3: row = (mat&1)*8 + (lane&7), colhalf = (mat>>1)*8
    uint32_t a_lo = ((((lane >> 3) & 1) * 8 + (lane & 7)) * RSTR + (lane >> 4) * 8) * 2;
    // B x4: mat = lane>>3: row(n) = (mat>>1)*8 + (lane&7), colhalf = (mat&1)*8
    uint32_t b_lo = (((lane >> 4) * 8 + (lane & 7)) * RSTR + ((lane >> 3) & 1) * 8) * 2;

    float acc[MT][4][4];
    #pragma unroll
    for (int mt = 0; mt < MT; mt++)
        #pragma unroll
        for (int nt = 0; nt < 4; nt++)
            #pragma unroll
            for (int r = 0; r < 4; r++) acc[mt][nt][r] = 0.f;

    int arow = tid >> 1;
    int acb  = (tid & 1) * 4;
    int brow = tid / TPRB;
    int bcb  = (tid % TPRB) * BCH;

    int nSt = K / KHC;
    uint32_t smb = smem_u32(smh);

    auto issue = [&](int s, int buf) {
        int k0 = s * KHC;
        uint32_t sa = smb + (uint32_t)buf * STAGEH * 2;
        uint32_t sbb = sa + TCM * RSTR * 2;
        const __half* asrc = Ab + (size_t)(m0 + arow) * lda + k0;
        uint32_t adst = sa + (arow * RSTR) * 2;
        #pragma unroll
        for (int j = 0; j < 4; j++) {
            int c = acb + j;
            asm volatile("cp.async.cg.shared.global [%0], [%1], 16;"
                         :: "r"(adst + c * 16), "l"(asrc + c * 8) : "memory");
        }
        const __half* bsrc = Bb + (size_t)(n0 + brow) * ldb + k0;
        uint32_t bdst = sbb + (brow * RSTR) * 2;
        #pragma unroll
        for (int j = 0; j < BCH; j++) {
            int c = bcb + j;
            asm volatile("cp.async.cg.shared.global [%0], [%1], 16;"
                         :: "r"(bdst + c * 16), "l"(bsrc + c * 8) : "memory");
        }
    };

    issue(0, 0);
    asm volatile("cp.async.commit_group;" ::: "memory");
    issue(1, 1);
    asm volatile("cp.async.commit_group;" ::: "memory");

    for (int s = 0; s < nSt; s++) {
        asm volatile("cp.async.wait_group 1;" ::: "memory");
        __syncthreads();
        if (s + 2 < nSt) issue(s + 2, (s + 2) % 3);
        asm volatile("cp.async.commit_group;" ::: "memory");

        uint32_t As_b = smb + (uint32_t)(s % 3) * STAGEH * 2;
        uint32_t Bs_b = As_b + TCM * RSTR * 2;
        #pragma unroll
        for (int kk = 0; kk < 4; kk++) {
            int k = kk * 16;
            uint32_t af[MT][4], bf[4][2];
            #pragma unroll
            for (int mt = 0; mt < MT; mt++) {
                uint32_t ad = As_b + (uint32_t)(((wm * WTM + mt * 16) * RSTR + k) * 2) + a_lo;
                asm volatile("ldmatrix.sync.aligned.m8n8.x4.shared.b16 {%0,%1,%2,%3}, [%4];"
                             : "=r"(af[mt][0]), "=r"(af[mt][1]), "=r"(af[mt][2]), "=r"(af[mt][3])
                             : "r"(ad));
            }
            uint32_t bd0 = Bs_b + (uint32_t)(((wn * 32) * RSTR + k) * 2) + b_lo;
            asm volatile("ldmatrix.sync.aligned.m8n8.x4.shared.b16 {%0,%1,%2,%3}, [%4];"
                         : "=r"(bf[0][0]), "=r"(bf[0][1]), "=r"(bf[1][0]), "=r"(bf[1][1])
                         : "r"(bd0));
            asm volatile("ldmatrix.sync.aligned.m8n8.x4.shared.b16 {%0,%1,%2,%3}, [%4];"
                         : "=r"(bf[2][0]), "=r"(bf[2][1]), "=r"(bf[3][0]), "=r"(bf[3][1])
                         : "r"(bd0 + 16 * RSTR * 2));
            #pragma unroll
            for (int mt = 0; mt < MT; mt++)
                #pragma unroll
                for (int nt = 0; nt < 4; nt++) {
                    asm volatile(
                        "mma.sync.aligned.m16n8k16.row.col.f32.f16.f16.f32 "
                        "{%0,%1,%2,%3}, {%4,%5,%6,%7}, {%8,%9}, {%0,%1,%2,%3};"
                        : "+f"(acc[mt][nt][0]), "+f"(acc[mt][nt][1]),
                          "+f"(acc[mt][nt][2]), "+f"(acc[mt][nt][3])
                        : "r"(af[mt][0]), "r"(af[mt][1]), "r"(af[mt][2]), "r"(af[mt][3]),
                          "r"(bf[nt][0]), "r"(bf[nt][1]));
                }
        }
        __syncthreads();
    }

    // epilogue
    #pragma unroll
    for (int mt = 0; mt < MT; mt++) {
        #pragma unroll
        for (int nt = 0; nt < 4; nt++) {
            int gn = n0 + wn * 32 + nt * 8 + tig * 2;
            float bv0 = biasb ? biasb[gn] : 0.f;
            float bv1 = biasb ? biasb[gn + 1] : 0.f;
            #pragma unroll
            for (int rh = 0; rh < 2; rh++) {
                int gm = m0 + wm * WTM + mt * 16 + grp + rh * 8;
                float v0 = acc[mt][nt][rh * 2 + 0] + bv0;
                float v1 = acc[mt][nt][rh * 2 + 1] + bv1;
                if (resid) {
                    v0 += resid[(size_t)gm * ldr + gn];
                    v1 += resid[(size_t)gm * ldr + gn + 1];
                }
                if (relu) { v0 = fmaxf(v0, 0.f); v1 = fmaxf(v1, 0.f); }
                if (Cfb) {
                    float2 o; o.x = v0; o.y = v1;
                    *(float2*)(Cfb + (size_t)gm * ldc + gn) = o;
                }
                if (Chb)
                    *(half2*)(Chb + (size_t)gm * ldc + gn) = __floats2half2_rn(v0, v1);
            }
        }
    }
}

// ---------------- LayerNorm (optional mask, optional fp16 copy) -------------
__global__ __launch_bounds__(256) void ln_kernel(
    const float* __restrict__ in, const float* __restrict__ gamma,
    const float* __restrict__ beta, const int* __restrict__ ids,
    float* __restrict__ out, __half* __restrict__ out16)
{
    __shared__ float red1[8], red2[8];
    __shared__ float bc1, bc2;
    int row = blockIdx.x, tid = threadIdx.x;
    const float* x = in + (size_t)row * PH;

    float v[3];
    #pragma unroll
    for (int j = 0; j < 3; j++) v[j] = x[tid + j * 256];

    float s = v[0] + v[1] + v[2];
    #pragma unroll
    for (int o = 16; o; o >>= 1) s += __shfl_xor_sync(0xffffffffu, s, o);
    if ((tid & 31) == 0) red1[tid >> 5] = s;
    __syncthreads();
    if (tid < 8) {
        float t = red1[tid];
        #pragma unroll
        for (int o = 4; o; o >>= 1) t += __shfl_xor_sync(0xffu, t, o);
        if (!tid) bc1 = t;
    }
    __syncthreads();
    float mu = bc1 * (1.0f / PH);

    float d0 = v[0] - mu, d1 = v[1] - mu, d2 = v[2] - mu;
    float sq = d0 * d0 + d1 * d1 + d2 * d2;
    #pragma unroll
    for (int o = 16; o; o >>= 1) sq += __shfl_xor_sync(0xffffffffu, sq, o);
    if ((tid & 31) == 0) red2[tid >> 5] = sq;
    __syncthreads();
    if (tid < 8) {
        float t = red2[tid];
        #pragma unroll
        for (int o = 4; o; o >>= 1) t += __shfl_xor_sync(0xffu, t, o);
        if (!tid) bc2 = t;
    }
    __syncthreads();
    float var = bc2 * (1.0f / PH);
    float rs = rsqrtf(var + 1e-5f);

    float mask = 1.0f;
    if (ids) {
        int a = ids[2 * row], b = ids[2 * row + 1];
        if (b - a <= 0) mask = 0.f;
    }
    #pragma unroll
    for (int j = 0; j < 3; j++) {
        int c = tid + j * 256;
        float o = ((v[j] - mu) * rs * gamma[c] + beta[c]) * mask;
        out[(size_t)row * PH + c] = o;
        if (out16) out16[(size_t)row * PH + c] = __float2half_rn(o);
    }
}

// ---------------- launch -----------------------------------------------------
#define SMEM_G128 (3 * (TCM + 128) * RSTR * 2)
#define SMEM_G64  (3 * (TCM + 64) * RSTR * 2)

extern "C" void kernel_launch(void* const* d_in, const int* in_sizes, int n_in,
                              void* d_out, int out_size) {
    const float* tok = (const float*)d_in[0];
    const int*   ids = (const int*)d_in[1];
    const float* q0  = (const float*)d_in[2];
    const float* inw = (const float*)d_in[3];
    const float* inb = (const float*)d_in[4];
    const float* ow  = (const float*)d_in[5];
    const float* ob  = (const float*)d_in[6];
    const float* lng = (const float*)d_in[7];
    const float* lnb = (const float*)d_in[8];
    const float* w1  = (const float*)d_in[9];
    const float* b1  = (const float*)d_in[10];
    const float* w2  = (const float*)d_in[11];
    const float* b2  = (const float*)d_in[12];
    float* out = (float*)d_out;

    __half *p_p16, *p_ctx16, *p_x116, *p_h16, *p_wv16, *p_wo16, *p_w116, *p_w216;
    float *p_att, *p_x1, *p_z;
    cudaGetSymbolAddress((void**)&p_p16,   g_p16);
    cudaGetSymbolAddress((void**)&p_ctx16, g_ctx16);
    cudaGetSymbolAddress((void**)&p_att,   g_att);
    cudaGetSymbolAddress((void**)&p_x1,    g_x1);
    cudaGetSymbolAddress((void**)&p_x116,  g_x116);
    cudaGetSymbolAddress((void**)&p_h16,   g_h16);
    cudaGetSymbolAddress((void**)&p_z,     g_z);
    cudaGetSymbolAddress((void**)&p_wv16,  g_wv16);
    cudaGetSymbolAddress((void**)&p_wo16,  g_wo16);
    cudaGetSymbolAddress((void**)&p_w116,  g_w116);
    cudaGetSymbolAddress((void**)&p_w216,  g_w216);

    cudaFuncSetAttribute(gemm_h_kernel<128>,
                         cudaFuncAttributeMaxDynamicSharedMemorySize, SMEM_G128);
    cudaFuncSetAttribute(gemm_h_kernel<64>,
                         cudaFuncAttributeMaxDynamicSharedMemorySize, SMEM_G64);

    // K0: prep
    qproj_kernel<<<96, 256>>>(inw, inb, q0);
    uprep_kernel<<<36, 256>>>(inw, inb);
    f2h4_kernel<<<dim3(512, 4), 256>>>(
        inw + (size_t)2 * PH * PH, p_wv16, PH * PH,
        ow, p_wo16, PH * PH,
        w1, p_w116, PFFN * PH,
        w2, p_w216, PH * PFFN);
    tokpe_tproj_kernel<<<PB * PSL / 4, 128>>>(tok);

    // K1: per-span scores/softmax/pooling -> p16
    span_kernel<<<PN, 192>>>(ids);

    // K2: ctx16 = p @ Wv^T + bv (batched over heads), N=64 per head
    gemm_h_kernel<64><<<dim3(1, PN / TCM, PNH), 256, SMEM_G64>>>(
        p_p16, p_wv16, inb + 2 * PH, (const float*)0, (float*)0, p_ctx16,
        PH, PH, PH, PH, 0,
        (long long)PN * PH, (long long)PHD * PH, PHD, PHD, 0);

    // K3: att = ctx @ O^T + ob + q0(broadcast)  (N=64 tiles -> 192 CTAs)
    gemm_h_kernel<64><<<dim3(PH / 64, PN / TCM, 1), 256, SMEM_G64>>>(
        p_ctx16, p_wo16, ob, q0, p_att, (__half*)0,
        PH, PH, PH, PH, 0, 0, 0, 0, 0, 0);

    // K4: x1 = LN(att); also x116
    ln_kernel<<<PN, 256>>>(p_att, lng, lnb, (const int*)0, p_x1, p_x116);

    // K5: h16 = relu(x1 @ W1^T + b1)
    gemm_h_kernel<128><<<dim3(PFFN / 128, PN / TCM, 1), 256, SMEM_G128>>>(
        p_x116, p_w116, b1, (const float*)0, (float*)0, p_h16,
        PH, PH, PH, PFFN, 0, 0, 0, 0, 0, 1);

    // K6: z = h @ W2^T + b2 + x1  (N=64 tiles -> 192 CTAs)
    gemm_h_kernel<64><<<dim3(PH / 64, PN / TCM, 1), 256, SMEM_G64>>>(
        p_h16, p_w216, b2, p_x1, p_z, (__half*)0,
        PFFN, PFFN, PFFN, PH, PH, 0, 0, 0, 0, 0);

    // K7: out = LN(z) masked by length>0
    ln_kernel<<<PN, 256>>>(p_z, lng, lnb, ids, out, (__half*)0);
}